// round 11
// baseline (speedup 1.0000x reference)
#include <cuda_runtime.h>
#include <cuda_bf16.h>
#include <cstdint>
#include <math.h>

#define BDIM 32
#define LDIM 8
#define SDIM 512
#define DDIM 256
#define EDIM 2048
#define NTOK (BDIM*LDIM*SDIM)   /* 131072 */
#define TOKL (BDIM*SDIM)        /* 16384 tokens per l */

// ---- device scratch ----
__device__ float      g_embedT[(size_t)LDIM*EDIM*DDIM];   // (L,E,D) fp32 codebook
__device__ float      g_enorm [(size_t)LDIM*EDIM];        // ||e||^2 fp32
__device__ int        g_ids   [NTOK];
__device__ int2       g_cand  [NTOK];                     // top-2 approx candidates
__device__ int        g_counts[(size_t)LDIM*EDIM];
__device__ long long  g_sum   [(size_t)LDIM*DDIM*EDIM];
__device__ unsigned long long g_diffacc;
__device__ float      g_nvals [LDIM];
// bf16 2-split planes
__device__ unsigned short g_A1[(size_t)NTOK*DDIM];
__device__ unsigned short g_A2[(size_t)NTOK*DDIM];
__device__ unsigned short g_B1[(size_t)LDIM*EDIM*DDIM];
__device__ unsigned short g_B2[(size_t)LDIM*EDIM*DDIM];

// =====================================================================
__device__ __forceinline__ uint32_t smem_addr_u32(const void* p) {
    uint32_t a;
    asm("{ .reg .u64 t; cvta.to.shared.u64 t, %1; cvt.u32.u64 %0, t; }" : "=r"(a) : "l"(p));
    return a;
}
__device__ __forceinline__ void cpasync16(uint32_t s, const void* g) {
    asm volatile("cp.async.cg.shared.global [%0], [%1], 16;" :: "r"(s), "l"(g));
}
#define CP_COMMIT() asm volatile("cp.async.commit_group;" ::: "memory")
#define CP_WAIT(n)  asm volatile("cp.async.wait_group %0;" :: "n"(n) : "memory")

__device__ __forceinline__ void ldsm4(uint32_t* r, uint32_t addr) {
    asm volatile("ldmatrix.sync.aligned.m8n8.x4.shared.b16 {%0,%1,%2,%3}, [%4];"
        : "=r"(r[0]), "=r"(r[1]), "=r"(r[2]), "=r"(r[3]) : "r"(addr));
}
__device__ __forceinline__ void mma16816(float* c, const uint32_t* a, uint32_t b0, uint32_t b1) {
    asm volatile("mma.sync.aligned.m16n8k16.row.col.f32.bf16.bf16.f32 "
        "{%0,%1,%2,%3}, {%4,%5,%6,%7}, {%8,%9}, {%0,%1,%2,%3};"
        : "+f"(c[0]), "+f"(c[1]), "+f"(c[2]), "+f"(c[3])
        : "r"(a[0]), "r"(a[1]), "r"(a[2]), "r"(a[3]), "r"(b0), "r"(b1));
}

__device__ __forceinline__ void split2(float v, unsigned short& a, unsigned short& b) {
    __nv_bfloat16 h1 = __float2bfloat16(v);
    float r1 = v - __bfloat162float(h1);
    __nv_bfloat16 h2 = __float2bfloat16(r1);
    a = __bfloat16_as_ushort(h1);
    b = __bfloat16_as_ushort(h2);
}

// Expand x -> A1, A2
__global__ void k_expand_x(const float* __restrict__ x) {
    int t = blockIdx.x;
    int i = threadIdx.x;           // 128 threads, 2 d each
    float2 v = *(const float2*)(x + (size_t)t*DDIM + 2*i);
    unsigned short a0,b0, a1,b1;
    split2(v.x, a0, b0);
    split2(v.y, a1, b1);
    size_t o = (size_t)t*(DDIM/2) + i;
    ((uint32_t*)g_A1)[o] = (uint32_t)a0 | ((uint32_t)a1 << 16);
    ((uint32_t*)g_A2)[o] = (uint32_t)b0 | ((uint32_t)b1 << 16);
}

// Transpose + expand embed -> B1, B2 + fp32 g_embedT
__global__ void k_expand_e(const float* __restrict__ embed) {
    __shared__ float tile[32][33];
    int l  = blockIdx.z;
    int e0 = blockIdx.x * 32;
    int d0 = blockIdx.y * 32;
    int tx = threadIdx.x, ty = threadIdx.y;   // 32 x 8
    const float* src = embed + (size_t)l*DDIM*EDIM;
    #pragma unroll
    for (int i = ty; i < 32; i += 8)
        tile[i][tx] = src[(size_t)(d0+i)*EDIM + e0 + tx];
    __syncthreads();
    #pragma unroll
    for (int i = ty; i < 32; i += 8) {
        float v = tile[tx][i];
        unsigned short h1, h2;
        split2(v, h1, h2);
        size_t idx = ((size_t)(l*EDIM + e0 + i))*DDIM + (d0 + tx);
        g_B1[idx] = h1; g_B2[idx] = h2;
        g_embedT[idx] = v;
    }
}

__global__ void k_enorm(const float* __restrict__ embed) {
    int idx = blockIdx.x*blockDim.x + threadIdx.x;
    int l = idx / EDIM, e = idx % EDIM;
    const float* src = embed + (size_t)l*DDIM*EDIM + e;
    float s = 0.f;
    #pragma unroll 8
    for (int d = 0; d < DDIM; d++) {
        float v = src[(size_t)d*EDIM];
        s += v*v;
    }
    g_enorm[idx] = s;
}

// =====================================================================
// HMMA fused GEMM + approx top-2. 64 tokens x 2048 codes per CTA.
// 256 threads = 8 warps (2 M x 4 N), warp tile 32x64; TWO CTAs per SM
// (SMEM 100KB/CTA, <=128 regs) so barriers/epilogues of one CTA overlap
// the other CTA's MMA stream. k-slab 32, depth-1 double buffer, one
// barrier per slab (round-6/10 proven skeleton). 80B row pad.
// 3 products A1B1+A1B2+A2B1.
// Stage: A1@0(5120) A2@5120 B1@10240(20480) B2@30720; STAGE=51200.
// =====================================================================
#define ST_A2   5120
#define ST_B1   10240
#define ST_B2   30720
#define STAGE   51200
#define SMEM_TOTAL (2*STAGE)

__device__ __forceinline__ void load_slab(uint32_t dst,
        const unsigned short* A1r, const unsigned short* A2r,
        const unsigned short* B1r, const unsigned short* B2r, int g, int tid) {
    int n0 = (g >> 3) << 8, kcol = (g & 7) << 5;
    {   // A planes: 64 rows x 32 bf16 = 256 chunks each
        int row = tid >> 2, q = tid & 3;
        const size_t go = (size_t)row*DDIM + kcol + q*8;
        uint32_t so = row*80 + q*16;
        cpasync16(dst + so,         A1r + go);
        cpasync16(dst + ST_A2 + so, A2r + go);
    }
    #pragma unroll
    for (int it = 0; it < 4; it++) {          // B planes: 1024 chunks each
        int c = it*256 + tid, row = c >> 2, q = c & 3;
        const size_t go = (size_t)(n0 + row)*DDIM + kcol + q*8;
        uint32_t so = row*80 + q*16;
        cpasync16(dst + ST_B1 + so, B1r + go);
        cpasync16(dst + ST_B2 + so, B2r + go);
    }
}

__global__ void __launch_bounds__(256, 2)
k_assign_mma(int dummy) {
    extern __shared__ unsigned char smem[];
    const uint32_t sb = smem_addr_u32(smem);
    int tid = threadIdx.x, lane = tid & 31, wid = tid >> 5;
    int wm = wid >> 2, wn = wid & 3;          // 2 x 4 warp grid
    int l  = blockIdx.y;
    int r0 = blockIdx.x * 64;
    int b = r0 >> 9, s0 = r0 & 511;
    size_t tokbase = ((size_t)(b*LDIM + l)*SDIM + s0);

    const unsigned short* A1r = g_A1 + tokbase*DDIM;
    const unsigned short* A2r = g_A2 + tokbase*DDIM;
    const unsigned short* B1r = g_B1 + (size_t)l*EDIM*DDIM;
    const unsigned short* B2r = g_B2 + (size_t)l*EDIM*DDIM;
    const float* en = g_enorm + l*EDIM;

    // prologue: slabs 0 and 1 in flight
    load_slab(sb,         A1r, A2r, B1r, B2r, 0, tid); CP_COMMIT();
    load_slab(sb + STAGE, A1r, A2r, B1r, B2r, 1, tid); CP_COMMIT();

    float bv0[4], bv1[4]; int bi0[4], bi1[4];
    #pragma unroll
    for (int i = 0; i < 4; i++) { bv0[i] = 3.4e38f; bv1[i] = 3.4e38f; bi0[i] = 0; bi1[i] = 0; }

    const uint32_t aAddr = (uint32_t)((wm*32 + (lane & 15))*80 + (lane >> 4)*16);
    const uint32_t bAddr = (uint32_t)(ST_B1 + (wn*64 + (lane & 7) + ((lane >> 4) & 1)*8)*80
                                      + ((lane >> 3) & 1)*16);
    float acc[2][8][4];

    for (int g = 0; g < 64; g++) {
        int ks = g & 7;
        if (ks == 0) {
            #pragma unroll
            for (int mf = 0; mf < 2; mf++)
                #pragma unroll
                for (int nf = 0; nf < 8; nf++)
                    #pragma unroll
                    for (int q = 0; q < 4; q++) acc[mf][nf][q] = 0.f;
        }
        if (g == 63) { CP_WAIT(0); } else { CP_WAIT(1); }
        __syncthreads();
        if (g + 1 < 64) {
            load_slab(sb + ((g+1) & 1)*STAGE, A1r, A2r, B1r, B2r, g + 1, tid);
            CP_COMMIT();
        }
        uint32_t stB = sb + (g & 1)*STAGE;
        uint32_t aB = stB + aAddr;
        uint32_t bB = stB + bAddr;
        #pragma unroll
        for (int kq = 0; kq < 2; kq++) {
            uint32_t a[2][4], bf[4][4], bf2[4][4];
            #pragma unroll
            for (int mf = 0; mf < 2; mf++) ldsm4(a[mf],   aB + mf*1280 + kq*32);
            #pragma unroll
            for (int nf = 0; nf < 4; nf++) ldsm4(bf[nf],  bB + nf*1280 + kq*32);
            #pragma unroll
            for (int nf = 0; nf < 4; nf++) ldsm4(bf2[nf], bB + (ST_B2-ST_B1) + nf*1280 + kq*32);
            #pragma unroll
            for (int mf = 0; mf < 2; mf++)
                #pragma unroll
                for (int nf = 0; nf < 4; nf++) {
                    mma16816(acc[mf][2*nf],   a[mf], bf[nf][0],  bf[nf][1]);
                    mma16816(acc[mf][2*nf+1], a[mf], bf[nf][2],  bf[nf][3]);
                    mma16816(acc[mf][2*nf],   a[mf], bf2[nf][0], bf2[nf][1]);
                    mma16816(acc[mf][2*nf+1], a[mf], bf2[nf][2], bf2[nf][3]);
                }
            #pragma unroll
            for (int mf = 0; mf < 2; mf++) ldsm4(a[mf], aB + ST_A2 + mf*1280 + kq*32);
            #pragma unroll
            for (int mf = 0; mf < 2; mf++)
                #pragma unroll
                for (int nf = 0; nf < 4; nf++) {
                    mma16816(acc[mf][2*nf],   a[mf], bf[nf][0], bf[nf][1]);
                    mma16816(acc[mf][2*nf+1], a[mf], bf[nf][2], bf[nf][3]);
                }
        }
        if (ks == 7) {
            int n0 = (g >> 3) << 8;
            #pragma unroll
            for (int nf = 0; nf < 8; nf++) {
                int col = n0 + wn*64 + nf*8 + 2*(lane & 3);
                float e0 = en[col], e1 = en[col + 1];
                #pragma unroll
                for (int mf = 0; mf < 2; mf++)
                    #pragma unroll
                    for (int h = 0; h < 2; h++) {
                        int s = mf*2 + h;
                        float v0 = fmaf(-2.0f, acc[mf][nf][2*h],     e0);
                        float v1 = fmaf(-2.0f, acc[mf][nf][2*h + 1], e1);
                        if (v0 < bv0[s]) { bv1[s]=bv0[s]; bi1[s]=bi0[s]; bv0[s]=v0; bi0[s]=col; }
                        else if (v0 < bv1[s]) { bv1[s]=v0; bi1[s]=col; }
                        if (v1 < bv0[s]) { bv1[s]=bv0[s]; bi1[s]=bi0[s]; bv0[s]=v1; bi0[s]=col+1; }
                        else if (v1 < bv1[s]) { bv1[s]=v1; bi1[s]=col+1; }
                    }
            }
        }
    }

    __syncthreads();
    float* redV = (float*)smem;                 // [64][16][2]
    int*   redI = (int*)(smem + 8192);
    int slot16 = wn*4 + (lane & 3);
    #pragma unroll
    for (int mf = 0; mf < 2; mf++)
        #pragma unroll
        for (int h = 0; h < 2; h++) {
            int s = mf*2 + h;
            int r = wm*32 + mf*16 + (lane >> 2) + h*8;
            redV[(r*16 + slot16)*2 + 0] = bv0[s];
            redV[(r*16 + slot16)*2 + 1] = bv1[s];
            redI[(r*16 + slot16)*2 + 0] = bi0[s];
            redI[(r*16 + slot16)*2 + 1] = bi1[s];
        }
    __syncthreads();
    if (tid < 64) {
        float b0 = 3.4e38f, b1v = 3.4e38f; int i0 = 0, i1 = 0;
        #pragma unroll
        for (int s = 0; s < 32; s++) {
            float v = redV[tid*32 + s]; int iv = redI[tid*32 + s];
            if (v < b0 || (v == b0 && iv < i0)) { b1v = b0; i1 = i0; b0 = v; i0 = iv; }
            else if ((v < b1v || (v == b1v && iv < i1)) && iv != i0) { b1v = v; i1 = iv; }
        }
        g_cand[tokbase + tid] = make_int2(i0, i1);
    }
}

// =====================================================================
// Exact fp32 rescore of the two candidates -> final ids
// =====================================================================
__global__ void k_rescore(const float* __restrict__ x, float* __restrict__ out_ids_f) {
    int w = threadIdx.x >> 5, lane = threadIdx.x & 31;
    int t = blockIdx.x*8 + w;
    int l = (t / SDIM) % LDIM;
    int2 c = g_cand[t];
    const float* xr = x + (size_t)t*DDIM;
    const float* e0 = g_embedT + ((size_t)l*EDIM + c.x)*DDIM;
    const float* e1 = g_embedT + ((size_t)l*EDIM + c.y)*DDIM;
    float d0 = 0.f, d1 = 0.f;
    #pragma unroll
    for (int i = 0; i < 8; i++) {
        float xv = xr[lane + 32*i];
        d0 += xv * e0[lane + 32*i];
        d1 += xv * e1[lane + 32*i];
    }
    #pragma unroll
    for (int o = 16; o > 0; o >>= 1) {
        d0 += __shfl_down_sync(0xffffffffu, d0, o);
        d1 += __shfl_down_sync(0xffffffffu, d1, o);
    }
    if (lane == 0) {
        const float* en = g_enorm + l*EDIM;
        float s0 = fmaf(-2.0f, d0, en[c.x]);
        float s1 = fmaf(-2.0f, d1, en[c.y]);
        int best = (s1 < s0 || (s1 == s0 && c.y < c.x)) ? c.y : c.x;
        g_ids[t] = best;
        out_ids_f[t] = (float)best;
    }
}

// =====================================================================
// scatter / tail kernels (unchanged, known-good)
// =====================================================================
__global__ void k_scatter(const float* __restrict__ x, float* __restrict__ out) {
    int t = blockIdx.x;
    int l = (t / SDIM) % LDIM;
    int e = g_ids[t];
    int d = threadIdx.x;

    float xv = x[(size_t)t*DDIM + d];
    float qv = g_embedT[((size_t)l*EDIM + e)*DDIM + d];
    out[(size_t)t*DDIM + d] = qv;

    long long fx = llrint((double)xv * 4294967296.0);
    atomicAdd((unsigned long long*)&g_sum[((size_t)l*DDIM + d)*EDIM + e],
              (unsigned long long)fx);
    if (d == 0) atomicAdd(&g_counts[l*EDIM + e], 1);

    if (l == LDIM - 1) {
        __shared__ long long sred[8];
        float df = (qv - xv)*(qv - xv);
        long long fd = llrint((double)df * 1048576.0);
        #pragma unroll
        for (int o = 16; o > 0; o >>= 1) fd += __shfl_down_sync(0xffffffffu, fd, o);
        if ((threadIdx.x & 31) == 0) sred[threadIdx.x >> 5] = fd;
        __syncthreads();
        if (threadIdx.x == 0) {
            long long s = 0;
            #pragma unroll
            for (int w = 0; w < 8; w++) s += sred[w];
            atomicAdd(&g_diffacc, (unsigned long long)s);
        }
    }
}

__global__ void k_ncs(const float* __restrict__ cs_in,
                      float* __restrict__ out_ncs, float* __restrict__ out_diff) {
    int l = blockIdx.x;
    __shared__ float red[32];
    float local = 0.f;
    for (int e = threadIdx.x; e < EDIM; e += blockDim.x) {
        float v = 0.999f*cs_in[l*EDIM+e] + 0.001f*(float)g_counts[l*EDIM+e];
        out_ncs[l*EDIM+e] = v;
        local += v;
    }
    #pragma unroll
    for (int o = 16; o > 0; o >>= 1) local += __shfl_down_sync(0xffffffffu, local, o);
    if ((threadIdx.x & 31) == 0) red[threadIdx.x >> 5] = local;
    __syncthreads();
    if (threadIdx.x < 32) {
        float v = red[threadIdx.x];
        #pragma unroll
        for (int o = 16; o > 0; o >>= 1) v += __shfl_down_sync(0xffffffffu, v, o);
        if (threadIdx.x == 0) g_nvals[l] = v;
    }
    if (l == 0 && threadIdx.x == 0) {
        double dsum = (double)(long long)g_diffacc * (1.0/1048576.0);
        out_diff[0] = (float)(2.0 * (dsum / (double)((size_t)BDIM*SDIM*DDIM)) / (double)LDIM);
    }
}

__global__ void k_final(const float* __restrict__ embed_avg,
                        const float* __restrict__ out_ncs,
                        float* __restrict__ out_ne, float* __restrict__ out_nea) {
    size_t i = (size_t)blockIdx.x*blockDim.x + threadIdx.x;
    int e = (int)(i % EDIM);
    int l = (int)(i / ((size_t)DDIM*EDIM));
    float sum = (float)((double)g_sum[i] * (1.0/4294967296.0));
    float nea = 0.999f*embed_avg[i] + 0.001f*sum;
    out_nea[i] = nea;
    float ncs = out_ncs[l*EDIM + e];
    float n   = g_nvals[l];
    float cs  = (ncs + 1e-5f) / (n + 0.02048f) * n;
    out_ne[i] = nea / cs;
}

// =====================================================================
extern "C" void kernel_launch(void* const* d_in, const int* in_sizes, int n_in,
                              void* d_out, int out_size) {
    const float* x     = (const float*)d_in[0];
    const float* embed = (const float*)d_in[1];
    const float* csz   = (const float*)d_in[2];
    const float* eavg  = (const float*)d_in[3];

    float* out      = (float*)d_out;
    float* out_main = out;
    float* out_diff = out + (size_t)33554432;
    float* out_ids  = out + (size_t)33554433;
    float* out_ne   = out_ids + (size_t)131072;
    float* out_ncs  = out_ne  + (size_t)4194304;
    float* out_nea  = out_ncs + (size_t)16384;

    cudaFuncSetAttribute(k_assign_mma, cudaFuncAttributeMaxDynamicSharedMemorySize,
                         SMEM_TOTAL);

    void *pSum, *pCnt, *pDiff;
    cudaGetSymbolAddress(&pSum,  g_sum);
    cudaGetSymbolAddress(&pCnt,  g_counts);
    cudaGetSymbolAddress(&pDiff, g_diffacc);
    cudaMemsetAsync(pSum,  0, (size_t)LDIM*DDIM*EDIM*sizeof(long long));
    cudaMemsetAsync(pCnt,  0, (size_t)LDIM*EDIM*sizeof(int));
    cudaMemsetAsync(pDiff, 0, sizeof(unsigned long long));

    dim3 tb(32, 8);
    k_enorm<<<(LDIM*EDIM)/256, 256>>>(embed);
    k_expand_x<<<NTOK, 128>>>(x);
    k_expand_e<<<dim3(EDIM/32, DDIM/32, LDIM), tb>>>(embed);
    k_assign_mma<<<dim3(TOKL/64, LDIM), 256, SMEM_TOTAL>>>(0);
    k_rescore<<<NTOK/8, 256>>>(x, out_ids);
    k_scatter<<<NTOK, 256>>>(x, out_main);
    k_ncs<<<LDIM, 1024>>>(csz, out_ncs, out_diff);
    k_final<<<(unsigned)(((size_t)LDIM*DDIM*EDIM)/256), 256>>>(eavg, out_ncs, out_ne, out_nea);
}

// round 12
// speedup vs baseline: 1.0757x; 1.0757x over previous
#include <cuda_runtime.h>
#include <cuda_bf16.h>
#include <cstdint>
#include <math.h>

#define BDIM 32
#define LDIM 8
#define SDIM 512
#define DDIM 256
#define EDIM 2048
#define NTOK (BDIM*LDIM*SDIM)   /* 131072 */
#define TOKL (BDIM*SDIM)        /* 16384 tokens per l */

// ---- device scratch ----
__device__ float      g_embedT[(size_t)LDIM*EDIM*DDIM];   // (L,E,D) fp32 codebook
__device__ float      g_enorm [(size_t)LDIM*EDIM];        // ||e||^2 fp32
__device__ int        g_ids   [NTOK];
__device__ int2       g_cand  [NTOK];                     // top-2 approx candidates
__device__ int        g_counts[(size_t)LDIM*EDIM];
__device__ long long  g_sum   [(size_t)LDIM*EDIM*DDIM];   // (L,E,D) fixed-point sums
__device__ unsigned long long g_diffacc;
__device__ float      g_nvals [LDIM];
// bf16 2-split planes
__device__ unsigned short g_A1[(size_t)NTOK*DDIM];
__device__ unsigned short g_A2[(size_t)NTOK*DDIM];
__device__ unsigned short g_B1[(size_t)LDIM*EDIM*DDIM];
__device__ unsigned short g_B2[(size_t)LDIM*EDIM*DDIM];

// =====================================================================
__device__ __forceinline__ uint32_t smem_addr_u32(const void* p) {
    uint32_t a;
    asm("{ .reg .u64 t; cvta.to.shared.u64 t, %1; cvt.u32.u64 %0, t; }" : "=r"(a) : "l"(p));
    return a;
}
__device__ __forceinline__ void cpasync16(uint32_t s, const void* g) {
    asm volatile("cp.async.cg.shared.global [%0], [%1], 16;" :: "r"(s), "l"(g));
}
#define CP_COMMIT() asm volatile("cp.async.commit_group;" ::: "memory")
#define CP_WAIT(n)  asm volatile("cp.async.wait_group %0;" :: "n"(n) : "memory")

__device__ __forceinline__ void ldsm4(uint32_t* r, uint32_t addr) {
    asm volatile("ldmatrix.sync.aligned.m8n8.x4.shared.b16 {%0,%1,%2,%3}, [%4];"
        : "=r"(r[0]), "=r"(r[1]), "=r"(r[2]), "=r"(r[3]) : "r"(addr));
}
__device__ __forceinline__ void mma16816(float* c, const uint32_t* a, uint32_t b0, uint32_t b1) {
    asm volatile("mma.sync.aligned.m16n8k16.row.col.f32.bf16.bf16.f32 "
        "{%0,%1,%2,%3}, {%4,%5,%6,%7}, {%8,%9}, {%0,%1,%2,%3};"
        : "+f"(c[0]), "+f"(c[1]), "+f"(c[2]), "+f"(c[3])
        : "r"(a[0]), "r"(a[1]), "r"(a[2]), "r"(a[3]), "r"(b0), "r"(b1));
}

__device__ __forceinline__ void split2(float v, unsigned short& a, unsigned short& b) {
    __nv_bfloat16 h1 = __float2bfloat16(v);
    float r1 = v - __bfloat162float(h1);
    __nv_bfloat16 h2 = __float2bfloat16(r1);
    a = __bfloat16_as_ushort(h1);
    b = __bfloat16_as_ushort(h2);
}

// Expand x -> A1, A2
__global__ void k_expand_x(const float* __restrict__ x) {
    int t = blockIdx.x;
    int i = threadIdx.x;           // 128 threads, 2 d each
    float2 v = *(const float2*)(x + (size_t)t*DDIM + 2*i);
    unsigned short a0,b0, a1,b1;
    split2(v.x, a0, b0);
    split2(v.y, a1, b1);
    size_t o = (size_t)t*(DDIM/2) + i;
    ((uint32_t*)g_A1)[o] = (uint32_t)a0 | ((uint32_t)a1 << 16);
    ((uint32_t*)g_A2)[o] = (uint32_t)b0 | ((uint32_t)b1 << 16);
}

// Transpose + expand embed -> B1, B2 + fp32 g_embedT
__global__ void k_expand_e(const float* __restrict__ embed) {
    __shared__ float tile[32][33];
    int l  = blockIdx.z;
    int e0 = blockIdx.x * 32;
    int d0 = blockIdx.y * 32;
    int tx = threadIdx.x, ty = threadIdx.y;   // 32 x 8
    const float* src = embed + (size_t)l*DDIM*EDIM;
    #pragma unroll
    for (int i = ty; i < 32; i += 8)
        tile[i][tx] = src[(size_t)(d0+i)*EDIM + e0 + tx];
    __syncthreads();
    #pragma unroll
    for (int i = ty; i < 32; i += 8) {
        float v = tile[tx][i];
        unsigned short h1, h2;
        split2(v, h1, h2);
        size_t idx = ((size_t)(l*EDIM + e0 + i))*DDIM + (d0 + tx);
        g_B1[idx] = h1; g_B2[idx] = h2;
        g_embedT[idx] = v;
    }
}

__global__ void k_enorm(const float* __restrict__ embed) {
    int idx = blockIdx.x*blockDim.x + threadIdx.x;
    int l = idx / EDIM, e = idx % EDIM;
    const float* src = embed + (size_t)l*DDIM*EDIM + e;
    float s = 0.f;
    #pragma unroll 8
    for (int d = 0; d < DDIM; d++) {
        float v = src[(size_t)d*EDIM];
        s += v*v;
    }
    g_enorm[idx] = s;
}

// =====================================================================
// HMMA fused GEMM + approx top-2 (round-10 config, best known).
// 128 tokens x 2048 codes per CTA; 512 threads = 16 warps (4x4), warp
// tile 32x64; k-slab 64, depth-1 double buffer, one barrier per slab.
// Row stride 144B. 3 products A1B1+A1B2+A2B1.
// Stage: A1@0(18432) A2@18432 B1@36864(36864) B2@73728; STAGE=110592.
// =====================================================================
#define ST_A2   18432
#define ST_B1   36864
#define ST_B2   73728
#define STAGE   110592
#define SMEM_TOTAL (2*STAGE)

__device__ __forceinline__ void load_slab(uint32_t dst,
        const unsigned short* A1r, const unsigned short* A2r,
        const unsigned short* B1r, const unsigned short* B2r, int g, int tid) {
    int n0 = (g >> 2) << 8, kcol = (g & 3) << 6;
    #pragma unroll
    for (int it = 0; it < 2; it++) {          // A planes: 1024 chunks each
        int c = it*512 + tid, row = c >> 3, q = c & 7;
        const size_t go = (size_t)row*DDIM + kcol + q*8;
        uint32_t so = row*144 + q*16;
        cpasync16(dst + so,         A1r + go);
        cpasync16(dst + ST_A2 + so, A2r + go);
    }
    #pragma unroll
    for (int it = 0; it < 4; it++) {          // B planes: 2048 chunks each
        int c = it*512 + tid, row = c >> 3, q = c & 7;
        const size_t go = (size_t)(n0 + row)*DDIM + kcol + q*8;
        uint32_t so = row*144 + q*16;
        cpasync16(dst + ST_B1 + so, B1r + go);
        cpasync16(dst + ST_B2 + so, B2r + go);
    }
}

__global__ void __launch_bounds__(512, 1)
k_assign_mma(int dummy) {
    extern __shared__ unsigned char smem[];
    const uint32_t sb = smem_addr_u32(smem);
    int tid = threadIdx.x, lane = tid & 31, wid = tid >> 5;
    int wm = wid >> 2, wn = wid & 3;          // 4 x 4 warp grid
    int l  = blockIdx.y;
    int r0 = blockIdx.x * 128;
    int b = r0 >> 9, s0 = r0 & 511;
    size_t tokbase = ((size_t)(b*LDIM + l)*SDIM + s0);

    const unsigned short* A1r = g_A1 + tokbase*DDIM;
    const unsigned short* A2r = g_A2 + tokbase*DDIM;
    const unsigned short* B1r = g_B1 + (size_t)l*EDIM*DDIM;
    const unsigned short* B2r = g_B2 + (size_t)l*EDIM*DDIM;
    const float* en = g_enorm + l*EDIM;

    // prologue: slabs 0 and 1 in flight
    load_slab(sb,         A1r, A2r, B1r, B2r, 0, tid); CP_COMMIT();
    load_slab(sb + STAGE, A1r, A2r, B1r, B2r, 1, tid); CP_COMMIT();

    float bv0[4], bv1[4]; int bi0[4], bi1[4];
    #pragma unroll
    for (int i = 0; i < 4; i++) { bv0[i] = 3.4e38f; bv1[i] = 3.4e38f; bi0[i] = 0; bi1[i] = 0; }

    const uint32_t aAddr = (uint32_t)((wm*32 + (lane & 15))*144 + (lane >> 4)*16);
    const uint32_t bAddr = (uint32_t)(ST_B1 + (wn*64 + (lane & 7) + ((lane >> 4) & 1)*8)*144
                                      + ((lane >> 3) & 1)*16);
    float acc[2][8][4];

    for (int g = 0; g < 32; g++) {
        int ks = g & 3;
        if (ks == 0) {
            #pragma unroll
            for (int mf = 0; mf < 2; mf++)
                #pragma unroll
                for (int nf = 0; nf < 8; nf++)
                    #pragma unroll
                    for (int q = 0; q < 4; q++) acc[mf][nf][q] = 0.f;
        }
        if (g == 31) { CP_WAIT(0); } else { CP_WAIT(1); }
        __syncthreads();
        if (g + 1 < 32) {
            load_slab(sb + ((g+1) & 1)*STAGE, A1r, A2r, B1r, B2r, g + 1, tid);
            CP_COMMIT();
        }
        uint32_t stB = sb + (g & 1)*STAGE;
        uint32_t aB = stB + aAddr;
        uint32_t bB = stB + bAddr;
        #pragma unroll
        for (int kq = 0; kq < 4; kq++) {
            uint32_t a[2][4], bf[4][4], bf2[4][4];
            #pragma unroll
            for (int mf = 0; mf < 2; mf++) ldsm4(a[mf],   aB + mf*2304 + kq*32);
            #pragma unroll
            for (int nf = 0; nf < 4; nf++) ldsm4(bf[nf],  bB + nf*2304 + kq*32);
            #pragma unroll
            for (int nf = 0; nf < 4; nf++) ldsm4(bf2[nf], bB + (ST_B2-ST_B1) + nf*2304 + kq*32);
            #pragma unroll
            for (int mf = 0; mf < 2; mf++)
                #pragma unroll
                for (int nf = 0; nf < 4; nf++) {
                    mma16816(acc[mf][2*nf],   a[mf], bf[nf][0],  bf[nf][1]);
                    mma16816(acc[mf][2*nf+1], a[mf], bf[nf][2],  bf[nf][3]);
                    mma16816(acc[mf][2*nf],   a[mf], bf2[nf][0], bf2[nf][1]);
                    mma16816(acc[mf][2*nf+1], a[mf], bf2[nf][2], bf2[nf][3]);
                }
            #pragma unroll
            for (int mf = 0; mf < 2; mf++) ldsm4(a[mf], aB + ST_A2 + mf*2304 + kq*32);
            #pragma unroll
            for (int mf = 0; mf < 2; mf++)
                #pragma unroll
                for (int nf = 0; nf < 4; nf++) {
                    mma16816(acc[mf][2*nf],   a[mf], bf[nf][0], bf[nf][1]);
                    mma16816(acc[mf][2*nf+1], a[mf], bf[nf][2], bf[nf][3]);
                }
        }
        if (ks == 3) {
            int n0 = (g >> 2) << 8;
            #pragma unroll
            for (int nf = 0; nf < 8; nf++) {
                int col = n0 + wn*64 + nf*8 + 2*(lane & 3);
                float e0 = en[col], e1 = en[col + 1];
                #pragma unroll
                for (int mf = 0; mf < 2; mf++)
                    #pragma unroll
                    for (int h = 0; h < 2; h++) {
                        int s = mf*2 + h;
                        float v0 = fmaf(-2.0f, acc[mf][nf][2*h],     e0);
                        float v1 = fmaf(-2.0f, acc[mf][nf][2*h + 1], e1);
                        if (v0 < bv0[s]) { bv1[s]=bv0[s]; bi1[s]=bi0[s]; bv0[s]=v0; bi0[s]=col; }
                        else if (v0 < bv1[s]) { bv1[s]=v0; bi1[s]=col; }
                        if (v1 < bv0[s]) { bv1[s]=bv0[s]; bi1[s]=bi0[s]; bv0[s]=v1; bi0[s]=col+1; }
                        else if (v1 < bv1[s]) { bv1[s]=v1; bi1[s]=col+1; }
                    }
            }
        }
    }

    __syncthreads();
    float* redV = (float*)smem;                 // [128][16][2]
    int*   redI = (int*)(smem + 16384);
    int slot16 = wn*4 + (lane & 3);
    #pragma unroll
    for (int mf = 0; mf < 2; mf++)
        #pragma unroll
        for (int h = 0; h < 2; h++) {
            int s = mf*2 + h;
            int r = wm*32 + mf*16 + (lane >> 2) + h*8;
            redV[(r*16 + slot16)*2 + 0] = bv0[s];
            redV[(r*16 + slot16)*2 + 1] = bv1[s];
            redI[(r*16 + slot16)*2 + 0] = bi0[s];
            redI[(r*16 + slot16)*2 + 1] = bi1[s];
        }
    __syncthreads();
    if (tid < 128) {
        float b0 = 3.4e38f, b1v = 3.4e38f; int i0 = 0, i1 = 0;
        #pragma unroll
        for (int s = 0; s < 32; s++) {
            float v = redV[tid*32 + s]; int iv = redI[tid*32 + s];
            if (v < b0 || (v == b0 && iv < i0)) { b1v = b0; i1 = i0; b0 = v; i0 = iv; }
            else if ((v < b1v || (v == b1v && iv < i1)) && iv != i0) { b1v = v; i1 = iv; }
        }
        g_cand[tokbase + tid] = make_int2(i0, i1);
    }
}

// =====================================================================
// Exact fp32 rescore of the two candidates -> final ids
// =====================================================================
__global__ void k_rescore(const float* __restrict__ x, float* __restrict__ out_ids_f) {
    int w = threadIdx.x >> 5, lane = threadIdx.x & 31;
    int t = blockIdx.x*8 + w;
    int l = (t / SDIM) % LDIM;
    int2 c = g_cand[t];
    const float* xr = x + (size_t)t*DDIM;
    const float* e0 = g_embedT + ((size_t)l*EDIM + c.x)*DDIM;
    const float* e1 = g_embedT + ((size_t)l*EDIM + c.y)*DDIM;
    float d0 = 0.f, d1 = 0.f;
    #pragma unroll
    for (int i = 0; i < 8; i++) {
        float xv = xr[lane + 32*i];
        d0 += xv * e0[lane + 32*i];
        d1 += xv * e1[lane + 32*i];
    }
    #pragma unroll
    for (int o = 16; o > 0; o >>= 1) {
        d0 += __shfl_down_sync(0xffffffffu, d0, o);
        d1 += __shfl_down_sync(0xffffffffu, d1, o);
    }
    if (lane == 0) {
        const float* en = g_enorm + l*EDIM;
        float s0 = fmaf(-2.0f, d0, en[c.x]);
        float s1 = fmaf(-2.0f, d1, en[c.y]);
        int best = (s1 < s0 || (s1 == s0 && c.y < c.x)) ? c.y : c.x;
        g_ids[t] = best;
        out_ids_f[t] = (float)best;
    }
}

// =====================================================================
// Scatter: g_sum now (L,E,D) -> each token's 256 atomic adds are
// CONSECUTIVE (8 sectors instead of 256), same line as the q gather.
// =====================================================================
__global__ void k_scatter(const float* __restrict__ x, float* __restrict__ out) {
    int t = blockIdx.x;
    int l = (t / SDIM) % LDIM;
    int e = g_ids[t];
    int d = threadIdx.x;

    float xv = x[(size_t)t*DDIM + d];
    size_t ced = ((size_t)l*EDIM + e)*DDIM + d;
    float qv = g_embedT[ced];
    out[(size_t)t*DDIM + d] = qv;

    long long fx = llrint((double)xv * 4294967296.0);
    atomicAdd((unsigned long long*)&g_sum[ced], (unsigned long long)fx);
    if (d == 0) atomicAdd(&g_counts[l*EDIM + e], 1);

    if (l == LDIM - 1) {
        __shared__ long long sred[8];
        float df = (qv - xv)*(qv - xv);
        long long fd = llrint((double)df * 1048576.0);
        #pragma unroll
        for (int o = 16; o > 0; o >>= 1) fd += __shfl_down_sync(0xffffffffu, fd, o);
        if ((threadIdx.x & 31) == 0) sred[threadIdx.x >> 5] = fd;
        __syncthreads();
        if (threadIdx.x == 0) {
            long long s = 0;
            #pragma unroll
            for (int w = 0; w < 8; w++) s += sred[w];
            atomicAdd(&g_diffacc, (unsigned long long)s);
        }
    }
}

__global__ void k_ncs(const float* __restrict__ cs_in,
                      float* __restrict__ out_ncs, float* __restrict__ out_diff) {
    int l = blockIdx.x;
    __shared__ float red[32];
    float local = 0.f;
    for (int e = threadIdx.x; e < EDIM; e += blockDim.x) {
        float v = 0.999f*cs_in[l*EDIM+e] + 0.001f*(float)g_counts[l*EDIM+e];
        out_ncs[l*EDIM+e] = v;
        local += v;
    }
    #pragma unroll
    for (int o = 16; o > 0; o >>= 1) local += __shfl_down_sync(0xffffffffu, local, o);
    if ((threadIdx.x & 31) == 0) red[threadIdx.x >> 5] = local;
    __syncthreads();
    if (threadIdx.x < 32) {
        float v = red[threadIdx.x];
        #pragma unroll
        for (int o = 16; o > 0; o >>= 1) v += __shfl_down_sync(0xffffffffu, v, o);
        if (threadIdx.x == 0) g_nvals[l] = v;
    }
    if (l == 0 && threadIdx.x == 0) {
        double dsum = (double)(long long)g_diffacc * (1.0/1048576.0);
        out_diff[0] = (float)(2.0 * (dsum / (double)((size_t)BDIM*SDIM*DDIM)) / (double)LDIM);
    }
}

// =====================================================================
// new_embed_avg / new_embed over (L,D,E): read g_sum (L,E,D) coalesced,
// transpose via smem tile, write (L,D,E) coalesced.
// =====================================================================
__global__ void k_final(const float* __restrict__ embed_avg,
                        const float* __restrict__ out_ncs,
                        float* __restrict__ out_ne, float* __restrict__ out_nea) {
    __shared__ long long tile[32][33];
    int l  = blockIdx.z;
    int e0 = blockIdx.x * 32;
    int d0 = blockIdx.y * 32;
    int tx = threadIdx.x, ty = threadIdx.y;   // 32 x 8
    #pragma unroll
    for (int i = ty; i < 32; i += 8)
        tile[i][tx] = g_sum[((size_t)(l*EDIM + e0 + i))*DDIM + d0 + tx];
    __syncthreads();
    float n   = g_nvals[l];
    float ncs = out_ncs[l*EDIM + e0 + tx];
    float cs  = (ncs + 1e-5f) / (n + 0.02048f) * n;
    #pragma unroll
    for (int i = ty; i < 32; i += 8) {
        size_t o = ((size_t)l*DDIM + d0 + i)*EDIM + e0 + tx;
        float sum = (float)((double)tile[tx][i] * (1.0/4294967296.0));
        float nea = 0.999f*embed_avg[o] + 0.001f*sum;
        out_nea[o] = nea;
        out_ne[o]  = nea / cs;
    }
}

// =====================================================================
extern "C" void kernel_launch(void* const* d_in, const int* in_sizes, int n_in,
                              void* d_out, int out_size) {
    const float* x     = (const float*)d_in[0];
    const float* embed = (const float*)d_in[1];
    const float* csz   = (const float*)d_in[2];
    const float* eavg  = (const float*)d_in[3];

    float* out      = (float*)d_out;
    float* out_main = out;
    float* out_diff = out + (size_t)33554432;
    float* out_ids  = out + (size_t)33554433;
    float* out_ne   = out_ids + (size_t)131072;
    float* out_ncs  = out_ne  + (size_t)4194304;
    float* out_nea  = out_ncs + (size_t)16384;

    cudaFuncSetAttribute(k_assign_mma, cudaFuncAttributeMaxDynamicSharedMemorySize,
                         SMEM_TOTAL);

    void *pSum, *pCnt, *pDiff;
    cudaGetSymbolAddress(&pSum,  g_sum);
    cudaGetSymbolAddress(&pCnt,  g_counts);
    cudaGetSymbolAddress(&pDiff, g_diffacc);
    cudaMemsetAsync(pSum,  0, (size_t)LDIM*EDIM*DDIM*sizeof(long long));
    cudaMemsetAsync(pCnt,  0, (size_t)LDIM*EDIM*sizeof(int));
    cudaMemsetAsync(pDiff, 0, sizeof(unsigned long long));

    dim3 tb(32, 8);
    k_enorm<<<(LDIM*EDIM)/256, 256>>>(embed);
    k_expand_x<<<NTOK, 128>>>(x);
    k_expand_e<<<dim3(EDIM/32, DDIM/32, LDIM), tb>>>(embed);
    k_assign_mma<<<dim3(TOKL/128, LDIM), 512, SMEM_TOTAL>>>(0);
    k_rescore<<<NTOK/8, 256>>>(x, out_ids);
    k_scatter<<<NTOK, 256>>>(x, out_main);
    k_ncs<<<LDIM, 1024>>>(csz, out_ncs, out_diff);
    k_final<<<dim3(EDIM/32, DDIM/32, LDIM), tb>>>(eavg, out_ncs, out_ne, out_nea);
}

// round 13
// speedup vs baseline: 1.7073x; 1.5871x over previous
#include <cuda_runtime.h>
#include <cuda_bf16.h>
#include <cstdint>
#include <math.h>

#define BDIM 32
#define LDIM 8
#define SDIM 512
#define DDIM 256
#define EDIM 2048
#define NTOK (BDIM*LDIM*SDIM)   /* 131072 */
#define TOKL (BDIM*SDIM)        /* 16384 tokens per l */

// ---- device scratch ----
__device__ float      g_embedT[(size_t)LDIM*EDIM*DDIM];   // (L,E,D) fp32 codebook
__device__ float      g_enorm [(size_t)LDIM*EDIM];        // ||e||^2 fp32
__device__ int        g_ids   [NTOK];
__device__ int4       g_cand  [NTOK];                     // top-4 approx candidates
__device__ int        g_counts[(size_t)LDIM*EDIM];
__device__ long long  g_sum   [(size_t)LDIM*EDIM*DDIM];   // (L,E,D) fixed-point sums
__device__ unsigned long long g_diffacc;
__device__ float      g_nvals [LDIM];
// single bf16 planes
__device__ unsigned short g_A1[(size_t)NTOK*DDIM];
__device__ unsigned short g_B1[(size_t)LDIM*EDIM*DDIM];

// =====================================================================
__device__ __forceinline__ uint32_t smem_addr_u32(const void* p) {
    uint32_t a;
    asm("{ .reg .u64 t; cvta.to.shared.u64 t, %1; cvt.u32.u64 %0, t; }" : "=r"(a) : "l"(p));
    return a;
}
__device__ __forceinline__ void cpasync16(uint32_t s, const void* g) {
    asm volatile("cp.async.cg.shared.global [%0], [%1], 16;" :: "r"(s), "l"(g));
}
#define CP_COMMIT() asm volatile("cp.async.commit_group;" ::: "memory")
#define CP_WAIT(n)  asm volatile("cp.async.wait_group %0;" :: "n"(n) : "memory")

__device__ __forceinline__ void ldsm4(uint32_t* r, uint32_t addr) {
    asm volatile("ldmatrix.sync.aligned.m8n8.x4.shared.b16 {%0,%1,%2,%3}, [%4];"
        : "=r"(r[0]), "=r"(r[1]), "=r"(r[2]), "=r"(r[3]) : "r"(addr));
}
__device__ __forceinline__ void mma16816(float* c, const uint32_t* a, uint32_t b0, uint32_t b1) {
    asm volatile("mma.sync.aligned.m16n8k16.row.col.f32.bf16.bf16.f32 "
        "{%0,%1,%2,%3}, {%4,%5,%6,%7}, {%8,%9}, {%0,%1,%2,%3};"
        : "+f"(c[0]), "+f"(c[1]), "+f"(c[2]), "+f"(c[3])
        : "r"(a[0]), "r"(a[1]), "r"(a[2]), "r"(a[3]), "r"(b0), "r"(b1));
}

// Expand x -> A1 (bf16 round)
__global__ void k_expand_x(const float* __restrict__ x) {
    int t = blockIdx.x;
    int i = threadIdx.x;           // 128 threads, 2 d each
    float2 v = *(const float2*)(x + (size_t)t*DDIM + 2*i);
    unsigned short a0 = __bfloat16_as_ushort(__float2bfloat16(v.x));
    unsigned short a1 = __bfloat16_as_ushort(__float2bfloat16(v.y));
    ((uint32_t*)g_A1)[(size_t)t*(DDIM/2) + i] = (uint32_t)a0 | ((uint32_t)a1 << 16);
}

// Transpose + expand embed -> B1 (bf16) + fp32 g_embedT
__global__ void k_expand_e(const float* __restrict__ embed) {
    __shared__ float tile[32][33];
    int l  = blockIdx.z;
    int e0 = blockIdx.x * 32;
    int d0 = blockIdx.y * 32;
    int tx = threadIdx.x, ty = threadIdx.y;   // 32 x 8
    const float* src = embed + (size_t)l*DDIM*EDIM;
    #pragma unroll
    for (int i = ty; i < 32; i += 8)
        tile[i][tx] = src[(size_t)(d0+i)*EDIM + e0 + tx];
    __syncthreads();
    #pragma unroll
    for (int i = ty; i < 32; i += 8) {
        float v = tile[tx][i];
        size_t idx = ((size_t)(l*EDIM + e0 + i))*DDIM + (d0 + tx);
        g_B1[idx] = __bfloat16_as_ushort(__float2bfloat16(v));
        g_embedT[idx] = v;
    }
}

__global__ void k_enorm(const float* __restrict__ embed) {
    int idx = blockIdx.x*blockDim.x + threadIdx.x;
    int l = idx / EDIM, e = idx % EDIM;
    const float* src = embed + (size_t)l*DDIM*EDIM + e;
    float s = 0.f;
    #pragma unroll 8
    for (int d = 0; d < DDIM; d++) {
        float v = src[(size_t)d*EDIM];
        s += v*v;
    }
    g_enorm[idx] = s;
}

// =====================================================================
// HMMA fused GEMM + approx top-4. 128 tokens x 2048 codes per CTA;
// 512 threads = 16 warps (4x4), warp tile 32x64; SINGLE bf16 product.
// k-slab 64, depth-1 double buffer, one barrier per slab, 144B row pad.
// Stage: A1@0(18432) B1@18432(36864); STAGE=55296.
// =====================================================================
#define ST_B1   18432
#define STAGE   55296
#define SMEM_TOTAL (2*STAGE)

__device__ __forceinline__ void load_slab(uint32_t dst,
        const unsigned short* A1r, const unsigned short* B1r, int g, int tid) {
    int n0 = (g >> 2) << 8, kcol = (g & 3) << 6;
    #pragma unroll
    for (int it = 0; it < 2; it++) {          // A plane: 1024 chunks
        int c = it*512 + tid, row = c >> 3, q = c & 7;
        cpasync16(dst + row*144 + q*16, A1r + (size_t)row*DDIM + kcol + q*8);
    }
    #pragma unroll
    for (int it = 0; it < 4; it++) {          // B plane: 2048 chunks
        int c = it*512 + tid, row = c >> 3, q = c & 7;
        cpasync16(dst + ST_B1 + row*144 + q*16, B1r + (size_t)(n0 + row)*DDIM + kcol + q*8);
    }
}

__global__ void __launch_bounds__(512, 1)
k_assign_mma(int dummy) {
    extern __shared__ unsigned char smem[];
    const uint32_t sb = smem_addr_u32(smem);
    int tid = threadIdx.x, lane = tid & 31, wid = tid >> 5;
    int wm = wid >> 2, wn = wid & 3;          // 4 x 4 warp grid
    int l  = blockIdx.y;
    int r0 = blockIdx.x * 128;
    int b = r0 >> 9, s0 = r0 & 511;
    size_t tokbase = ((size_t)(b*LDIM + l)*SDIM + s0);

    const unsigned short* A1r = g_A1 + tokbase*DDIM;
    const unsigned short* B1r = g_B1 + (size_t)l*EDIM*DDIM;
    const float* en = g_enorm + l*EDIM;

    load_slab(sb,         A1r, B1r, 0, tid); CP_COMMIT();
    load_slab(sb + STAGE, A1r, B1r, 1, tid); CP_COMMIT();

    float bv0[4], bv1[4]; int bi0[4], bi1[4];
    #pragma unroll
    for (int i = 0; i < 4; i++) { bv0[i] = 3.4e38f; bv1[i] = 3.4e38f; bi0[i] = 0; bi1[i] = 0; }

    const uint32_t aAddr = (uint32_t)((wm*32 + (lane & 15))*144 + (lane >> 4)*16);
    const uint32_t bAddr = (uint32_t)(ST_B1 + (wn*64 + (lane & 7) + ((lane >> 4) & 1)*8)*144
                                      + ((lane >> 3) & 1)*16);
    float acc[2][8][4];

    for (int g = 0; g < 32; g++) {
        int ks = g & 3;
        if (ks == 0) {
            #pragma unroll
            for (int mf = 0; mf < 2; mf++)
                #pragma unroll
                for (int nf = 0; nf < 8; nf++)
                    #pragma unroll
                    for (int q = 0; q < 4; q++) acc[mf][nf][q] = 0.f;
        }
        if (g == 31) { CP_WAIT(0); } else { CP_WAIT(1); }
        __syncthreads();
        if (g + 1 < 32) {
            load_slab(sb + ((g+1) & 1)*STAGE, A1r, B1r, g + 1, tid);
            CP_COMMIT();
        }
        uint32_t stB = sb + (g & 1)*STAGE;
        uint32_t aB = stB + aAddr;
        uint32_t bB = stB + bAddr;
        #pragma unroll
        for (int kq = 0; kq < 4; kq++) {
            uint32_t a[2][4], bf[4][4];
            #pragma unroll
            for (int mf = 0; mf < 2; mf++) ldsm4(a[mf],  aB + mf*2304 + kq*32);
            #pragma unroll
            for (int nf = 0; nf < 4; nf++) ldsm4(bf[nf], bB + nf*2304 + kq*32);
            #pragma unroll
            for (int mf = 0; mf < 2; mf++)
                #pragma unroll
                for (int nf = 0; nf < 4; nf++) {
                    mma16816(acc[mf][2*nf],   a[mf], bf[nf][0], bf[nf][1]);
                    mma16816(acc[mf][2*nf+1], a[mf], bf[nf][2], bf[nf][3]);
                }
        }
        if (ks == 3) {
            int n0 = (g >> 2) << 8;
            #pragma unroll
            for (int nf = 0; nf < 8; nf++) {
                int col = n0 + wn*64 + nf*8 + 2*(lane & 3);
                float e0 = en[col], e1 = en[col + 1];
                #pragma unroll
                for (int mf = 0; mf < 2; mf++)
                    #pragma unroll
                    for (int h = 0; h < 2; h++) {
                        int s = mf*2 + h;
                        float v0 = fmaf(-2.0f, acc[mf][nf][2*h],     e0);
                        float v1 = fmaf(-2.0f, acc[mf][nf][2*h + 1], e1);
                        if (v0 < bv0[s]) { bv1[s]=bv0[s]; bi1[s]=bi0[s]; bv0[s]=v0; bi0[s]=col; }
                        else if (v0 < bv1[s]) { bv1[s]=v0; bi1[s]=col; }
                        if (v1 < bv0[s]) { bv1[s]=bv0[s]; bi1[s]=bi0[s]; bv0[s]=v1; bi0[s]=col+1; }
                        else if (v1 < bv1[s]) { bv1[s]=v1; bi1[s]=col+1; }
                    }
            }
        }
    }

    __syncthreads();
    float* redV = (float*)smem;                 // [128][16][2]
    int*   redI = (int*)(smem + 16384);
    int slot16 = wn*4 + (lane & 3);
    #pragma unroll
    for (int mf = 0; mf < 2; mf++)
        #pragma unroll
        for (int h = 0; h < 2; h++) {
            int s = mf*2 + h;
            int r = wm*32 + mf*16 + (lane >> 2) + h*8;
            redV[(r*16 + slot16)*2 + 0] = bv0[s];
            redV[(r*16 + slot16)*2 + 1] = bv1[s];
            redI[(r*16 + slot16)*2 + 0] = bi0[s];
            redI[(r*16 + slot16)*2 + 1] = bi1[s];
        }
    __syncthreads();
    if (tid < 128) {
        float tv0=3.4e38f, tv1=3.4e38f, tv2=3.4e38f, tv3=3.4e38f;
        int   ti0=0, ti1=0, ti2=0, ti3=0;
        #pragma unroll
        for (int s = 0; s < 32; s++) {
            float v = redV[tid*32 + s]; int iv = redI[tid*32 + s];
            if (v < tv3 || (v == tv3 && iv < ti3)) {
                tv3 = v; ti3 = iv;
                if (tv3 < tv2 || (tv3 == tv2 && ti3 < ti2)) {
                    float tv = tv2; int ti = ti2; tv2 = tv3; ti2 = ti3; tv3 = tv; ti3 = ti; }
                if (tv2 < tv1 || (tv2 == tv1 && ti2 < ti1)) {
                    float tv = tv1; int ti = ti1; tv1 = tv2; ti1 = ti2; tv2 = tv; ti2 = ti; }
                if (tv1 < tv0 || (tv1 == tv0 && ti1 < ti0)) {
                    float tv = tv0; int ti = ti0; tv0 = tv1; ti0 = ti1; tv1 = tv; ti1 = ti; }
            }
        }
        g_cand[tokbase + tid] = make_int4(ti0, ti1, ti2, ti3);
    }
}

// =====================================================================
// Exact fp32 rescore of the four candidates -> final ids
// =====================================================================
__global__ void k_rescore(const float* __restrict__ x, float* __restrict__ out_ids_f) {
    int w = threadIdx.x >> 5, lane = threadIdx.x & 31;
    int t = blockIdx.x*8 + w;
    int l = (t / SDIM) % LDIM;
    int4 c = g_cand[t];
    const float* xr = x + (size_t)t*DDIM;
    const float* e0 = g_embedT + ((size_t)l*EDIM + c.x)*DDIM;
    const float* e1 = g_embedT + ((size_t)l*EDIM + c.y)*DDIM;
    const float* e2 = g_embedT + ((size_t)l*EDIM + c.z)*DDIM;
    const float* e3 = g_embedT + ((size_t)l*EDIM + c.w)*DDIM;
    float d0 = 0.f, d1 = 0.f, d2 = 0.f, d3 = 0.f;
    #pragma unroll
    for (int i = 0; i < 8; i++) {
        float xv = xr[lane + 32*i];
        d0 += xv * e0[lane + 32*i];
        d1 += xv * e1[lane + 32*i];
        d2 += xv * e2[lane + 32*i];
        d3 += xv * e3[lane + 32*i];
    }
    #pragma unroll
    for (int o = 16; o > 0; o >>= 1) {
        d0 += __shfl_down_sync(0xffffffffu, d0, o);
        d1 += __shfl_down_sync(0xffffffffu, d1, o);
        d2 += __shfl_down_sync(0xffffffffu, d2, o);
        d3 += __shfl_down_sync(0xffffffffu, d3, o);
    }
    if (lane == 0) {
        const float* en = g_enorm + l*EDIM;
        float s0 = fmaf(-2.0f, d0, en[c.x]);
        float s1 = fmaf(-2.0f, d1, en[c.y]);
        float s2 = fmaf(-2.0f, d2, en[c.z]);
        float s3 = fmaf(-2.0f, d3, en[c.w]);
        float bs = s0; int bi = c.x;
        if (s1 < bs || (s1 == bs && c.y < bi)) { bs = s1; bi = c.y; }
        if (s2 < bs || (s2 == bs && c.z < bi)) { bs = s2; bi = c.z; }
        if (s3 < bs || (s3 == bs && c.w < bi)) { bs = s3; bi = c.w; }
        g_ids[t] = bi;
        out_ids_f[t] = (float)bi;
    }
}

// =====================================================================
// scatter / tail kernels (round-12 versions)
// =====================================================================
__global__ void k_scatter(const float* __restrict__ x, float* __restrict__ out) {
    int t = blockIdx.x;
    int l = (t / SDIM) % LDIM;
    int e = g_ids[t];
    int d = threadIdx.x;

    float xv = x[(size_t)t*DDIM + d];
    size_t ced = ((size_t)l*EDIM + e)*DDIM + d;
    float qv = g_embedT[ced];
    out[(size_t)t*DDIM + d] = qv;

    long long fx = llrint((double)xv * 4294967296.0);
    atomicAdd((unsigned long long*)&g_sum[ced], (unsigned long long)fx);
    if (d == 0) atomicAdd(&g_counts[l*EDIM + e], 1);

    if (l == LDIM - 1) {
        __shared__ long long sred[8];
        float df = (qv - xv)*(qv - xv);
        long long fd = llrint((double)df * 1048576.0);
        #pragma unroll
        for (int o = 16; o > 0; o >>= 1) fd += __shfl_down_sync(0xffffffffu, fd, o);
        if ((threadIdx.x & 31) == 0) sred[threadIdx.x >> 5] = fd;
        __syncthreads();
        if (threadIdx.x == 0) {
            long long s = 0;
            #pragma unroll
            for (int w = 0; w < 8; w++) s += sred[w];
            atomicAdd(&g_diffacc, (unsigned long long)s);
        }
    }
}

__global__ void k_ncs(const float* __restrict__ cs_in,
                      float* __restrict__ out_ncs, float* __restrict__ out_diff) {
    int l = blockIdx.x;
    __shared__ float red[32];
    float local = 0.f;
    for (int e = threadIdx.x; e < EDIM; e += blockDim.x) {
        float v = 0.999f*cs_in[l*EDIM+e] + 0.001f*(float)g_counts[l*EDIM+e];
        out_ncs[l*EDIM+e] = v;
        local += v;
    }
    #pragma unroll
    for (int o = 16; o > 0; o >>= 1) local += __shfl_down_sync(0xffffffffu, local, o);
    if ((threadIdx.x & 31) == 0) red[threadIdx.x >> 5] = local;
    __syncthreads();
    if (threadIdx.x < 32) {
        float v = red[threadIdx.x];
        #pragma unroll
        for (int o = 16; o > 0; o >>= 1) v += __shfl_down_sync(0xffffffffu, v, o);
        if (threadIdx.x == 0) g_nvals[l] = v;
    }
    if (l == 0 && threadIdx.x == 0) {
        double dsum = (double)(long long)g_diffacc * (1.0/1048576.0);
        out_diff[0] = (float)(2.0 * (dsum / (double)((size_t)BDIM*SDIM*DDIM)) / (double)LDIM);
    }
}

__global__ void k_final(const float* __restrict__ embed_avg,
                        const float* __restrict__ out_ncs,
                        float* __restrict__ out_ne, float* __restrict__ out_nea) {
    __shared__ long long tile[32][33];
    int l  = blockIdx.z;
    int e0 = blockIdx.x * 32;
    int d0 = blockIdx.y * 32;
    int tx = threadIdx.x, ty = threadIdx.y;   // 32 x 8
    #pragma unroll
    for (int i = ty; i < 32; i += 8)
        tile[i][tx] = g_sum[((size_t)(l*EDIM + e0 + i))*DDIM + d0 + tx];
    __syncthreads();
    float n   = g_nvals[l];
    float ncs = out_ncs[l*EDIM + e0 + tx];
    float cs  = (ncs + 1e-5f) / (n + 0.02048f) * n;
    #pragma unroll
    for (int i = ty; i < 32; i += 8) {
        size_t o = ((size_t)l*DDIM + d0 + i)*EDIM + e0 + tx;
        float sum = (float)((double)tile[tx][i] * (1.0/4294967296.0));
        float nea = 0.999f*embed_avg[o] + 0.001f*sum;
        out_nea[o] = nea;
        out_ne[o]  = nea / cs;
    }
}

// =====================================================================
extern "C" void kernel_launch(void* const* d_in, const int* in_sizes, int n_in,
                              void* d_out, int out_size) {
    const float* x     = (const float*)d_in[0];
    const float* embed = (const float*)d_in[1];
    const float* csz   = (const float*)d_in[2];
    const float* eavg  = (const float*)d_in[3];

    float* out      = (float*)d_out;
    float* out_main = out;
    float* out_diff = out + (size_t)33554432;
    float* out_ids  = out + (size_t)33554433;
    float* out_ne   = out_ids + (size_t)131072;
    float* out_ncs  = out_ne  + (size_t)4194304;
    float* out_nea  = out_ncs + (size_t)16384;

    cudaFuncSetAttribute(k_assign_mma, cudaFuncAttributeMaxDynamicSharedMemorySize,
                         SMEM_TOTAL);

    void *pSum, *pCnt, *pDiff;
    cudaGetSymbolAddress(&pSum,  g_sum);
    cudaGetSymbolAddress(&pCnt,  g_counts);
    cudaGetSymbolAddress(&pDiff, g_diffacc);
    cudaMemsetAsync(pSum,  0, (size_t)LDIM*EDIM*DDIM*sizeof(long long));
    cudaMemsetAsync(pCnt,  0, (size_t)LDIM*EDIM*sizeof(int));
    cudaMemsetAsync(pDiff, 0, sizeof(unsigned long long));

    dim3 tb(32, 8);
    k_enorm<<<(LDIM*EDIM)/256, 256>>>(embed);
    k_expand_x<<<NTOK, 128>>>(x);
    k_expand_e<<<dim3(EDIM/32, DDIM/32, LDIM), tb>>>(embed);
    k_assign_mma<<<dim3(TOKL/128, LDIM), 512, SMEM_TOTAL>>>(0);
    k_rescore<<<NTOK/8, 256>>>(x, out_ids);
    k_scatter<<<NTOK, 256>>>(x, out_main);
    k_ncs<<<LDIM, 1024>>>(csz, out_ncs, out_diff);
    k_final<<<dim3(EDIM/32, DDIM/32, LDIM), tb>>>(eavg, out_ncs, out_ne, out_nea);
}

// round 14
// speedup vs baseline: 1.7450x; 1.0221x over previous
#include <cuda_runtime.h>
#include <cuda_bf16.h>
#include <cstdint>
#include <math.h>

#define BDIM 32
#define LDIM 8
#define SDIM 512
#define DDIM 256
#define EDIM 2048
#define NTOK (BDIM*LDIM*SDIM)   /* 131072 */
#define TOKL (BDIM*SDIM)        /* 16384 tokens per l */

// ---- device scratch ----
__device__ float      g_embedT[(size_t)LDIM*EDIM*DDIM];   // (L,E,D) fp32 codebook
__device__ float      g_enorm [(size_t)LDIM*EDIM];        // ||e||^2 fp32
__device__ int4       g_cand  [NTOK];                     // top-4 approx candidates
__device__ int        g_counts[(size_t)LDIM*EDIM];
__device__ long long  g_sum   [(size_t)LDIM*EDIM*DDIM];   // (L,E,D) fixed-point sums
__device__ unsigned long long g_diffacc;
__device__ float      g_nvals [LDIM];
// single bf16 planes
__device__ unsigned short g_A1[(size_t)NTOK*DDIM];
__device__ unsigned short g_B1[(size_t)LDIM*EDIM*DDIM];

// =====================================================================
__device__ __forceinline__ uint32_t smem_addr_u32(const void* p) {
    uint32_t a;
    asm("{ .reg .u64 t; cvta.to.shared.u64 t, %1; cvt.u32.u64 %0, t; }" : "=r"(a) : "l"(p));
    return a;
}
__device__ __forceinline__ void cpasync16(uint32_t s, const void* g) {
    asm volatile("cp.async.cg.shared.global [%0], [%1], 16;" :: "r"(s), "l"(g));
}
#define CP_COMMIT() asm volatile("cp.async.commit_group;" ::: "memory")
#define CP_WAIT(n)  asm volatile("cp.async.wait_group %0;" :: "n"(n) : "memory")

__device__ __forceinline__ void ldsm4(uint32_t* r, uint32_t addr) {
    asm volatile("ldmatrix.sync.aligned.m8n8.x4.shared.b16 {%0,%1,%2,%3}, [%4];"
        : "=r"(r[0]), "=r"(r[1]), "=r"(r[2]), "=r"(r[3]) : "r"(addr));
}
__device__ __forceinline__ void mma16816(float* c, const uint32_t* a, uint32_t b0, uint32_t b1) {
    asm volatile("mma.sync.aligned.m16n8k16.row.col.f32.bf16.bf16.f32 "
        "{%0,%1,%2,%3}, {%4,%5,%6,%7}, {%8,%9}, {%0,%1,%2,%3};"
        : "+f"(c[0]), "+f"(c[1]), "+f"(c[2]), "+f"(c[3])
        : "r"(a[0]), "r"(a[1]), "r"(a[2]), "r"(a[3]), "r"(b0), "r"(b1));
}

// Expand x -> A1 (bf16 round)
__global__ void k_expand_x(const float* __restrict__ x) {
    int t = blockIdx.x;
    int i = threadIdx.x;           // 128 threads, 2 d each
    float2 v = *(const float2*)(x + (size_t)t*DDIM + 2*i);
    unsigned short a0 = __bfloat16_as_ushort(__float2bfloat16(v.x));
    unsigned short a1 = __bfloat16_as_ushort(__float2bfloat16(v.y));
    ((uint32_t*)g_A1)[(size_t)t*(DDIM/2) + i] = (uint32_t)a0 | ((uint32_t)a1 << 16);
}

// Transpose + expand embed -> B1 (bf16) + fp32 g_embedT
__global__ void k_expand_e(const float* __restrict__ embed) {
    __shared__ float tile[32][33];
    int l  = blockIdx.z;
    int e0 = blockIdx.x * 32;
    int d0 = blockIdx.y * 32;
    int tx = threadIdx.x, ty = threadIdx.y;   // 32 x 8
    const float* src = embed + (size_t)l*DDIM*EDIM;
    #pragma unroll
    for (int i = ty; i < 32; i += 8)
        tile[i][tx] = src[(size_t)(d0+i)*EDIM + e0 + tx];
    __syncthreads();
    #pragma unroll
    for (int i = ty; i < 32; i += 8) {
        float v = tile[tx][i];
        size_t idx = ((size_t)(l*EDIM + e0 + i))*DDIM + (d0 + tx);
        g_B1[idx] = __bfloat16_as_ushort(__float2bfloat16(v));
        g_embedT[idx] = v;
    }
}

__global__ void k_enorm(const float* __restrict__ embed) {
    int idx = blockIdx.x*blockDim.x + threadIdx.x;
    int l = idx / EDIM, e = idx % EDIM;
    const float* src = embed + (size_t)l*DDIM*EDIM + e;
    float s = 0.f;
    #pragma unroll 8
    for (int d = 0; d < DDIM; d++) {
        float v = src[(size_t)d*EDIM];
        s += v*v;
    }
    g_enorm[idx] = s;
}

// =====================================================================
// HMMA fused GEMM + approx top-4. 128 tokens x 2048 codes per CTA;
// 512 threads = 16 warps (4x4), warp tile 32x64; single bf16 product.
// k-slab 128 (16 slabs -> half the barrier/wait events of round 13).
// Row pad 272B (odd 16B phase -> conflict-free ldmatrix).
// Stage: A1@0(34816) B1@34816(69632); STAGE=104448.
// =====================================================================
#define ST_B1   34816
#define STAGE   104448
#define SMEM_TOTAL (2*STAGE)

__device__ __forceinline__ void load_slab(uint32_t dst,
        const unsigned short* A1r, const unsigned short* B1r, int g, int tid) {
    int n0 = (g >> 1) << 8, kcol = (g & 1) << 7;
    #pragma unroll
    for (int it = 0; it < 4; it++) {          // A plane: 2048 chunks
        int c = it*512 + tid, row = c >> 4, q = c & 15;
        cpasync16(dst + row*272 + q*16, A1r + (size_t)row*DDIM + kcol + q*8);
    }
    #pragma unroll
    for (int it = 0; it < 8; it++) {          // B plane: 4096 chunks
        int c = it*512 + tid, row = c >> 4, q = c & 15;
        cpasync16(dst + ST_B1 + row*272 + q*16, B1r + (size_t)(n0 + row)*DDIM + kcol + q*8);
    }
}

__global__ void __launch_bounds__(512, 1)
k_assign_mma(int dummy) {
    extern __shared__ unsigned char smem[];
    const uint32_t sb = smem_addr_u32(smem);
    int tid = threadIdx.x, lane = tid & 31, wid = tid >> 5;
    int wm = wid >> 2, wn = wid & 3;          // 4 x 4 warp grid
    int l  = blockIdx.y;
    int r0 = blockIdx.x * 128;
    int b = r0 >> 9, s0 = r0 & 511;
    size_t tokbase = ((size_t)(b*LDIM + l)*SDIM + s0);

    const unsigned short* A1r = g_A1 + tokbase*DDIM;
    const unsigned short* B1r = g_B1 + (size_t)l*EDIM*DDIM;
    const float* en = g_enorm + l*EDIM;

    load_slab(sb,         A1r, B1r, 0, tid); CP_COMMIT();
    load_slab(sb + STAGE, A1r, B1r, 1, tid); CP_COMMIT();

    float bv0[4], bv1[4]; int bi0[4], bi1[4];
    #pragma unroll
    for (int i = 0; i < 4; i++) { bv0[i] = 3.4e38f; bv1[i] = 3.4e38f; bi0[i] = 0; bi1[i] = 0; }

    const uint32_t aAddr = (uint32_t)((wm*32 + (lane & 15))*272 + (lane >> 4)*16);
    const uint32_t bAddr = (uint32_t)(ST_B1 + (wn*64 + (lane & 7) + ((lane >> 4) & 1)*8)*272
                                      + ((lane >> 3) & 1)*16);
    float acc[2][8][4];

    for (int g = 0; g < 16; g++) {
        int ks = g & 1;
        if (ks == 0) {
            #pragma unroll
            for (int mf = 0; mf < 2; mf++)
                #pragma unroll
                for (int nf = 0; nf < 8; nf++)
                    #pragma unroll
                    for (int q = 0; q < 4; q++) acc[mf][nf][q] = 0.f;
        }
        if (g == 15) { CP_WAIT(0); } else { CP_WAIT(1); }
        __syncthreads();
        if (g + 1 < 16) {
            load_slab(sb + ((g+1) & 1)*STAGE, A1r, B1r, g + 1, tid);
            CP_COMMIT();
        }
        uint32_t stB = sb + (g & 1)*STAGE;
        uint32_t aB = stB + aAddr;
        uint32_t bB = stB + bAddr;
        #pragma unroll
        for (int kq = 0; kq < 8; kq++) {
            uint32_t a[2][4], bf[4][4];
            #pragma unroll
            for (int mf = 0; mf < 2; mf++) ldsm4(a[mf],  aB + mf*4352 + kq*32);
            #pragma unroll
            for (int nf = 0; nf < 4; nf++) ldsm4(bf[nf], bB + nf*4352 + kq*32);
            #pragma unroll
            for (int mf = 0; mf < 2; mf++)
                #pragma unroll
                for (int nf = 0; nf < 4; nf++) {
                    mma16816(acc[mf][2*nf],   a[mf], bf[nf][0], bf[nf][1]);
                    mma16816(acc[mf][2*nf+1], a[mf], bf[nf][2], bf[nf][3]);
                }
        }
        if (ks == 1) {
            int n0 = (g >> 1) << 8;
            #pragma unroll
            for (int nf = 0; nf < 8; nf++) {
                int col = n0 + wn*64 + nf*8 + 2*(lane & 3);
                float e0 = en[col], e1 = en[col + 1];
                #pragma unroll
                for (int mf = 0; mf < 2; mf++)
                    #pragma unroll
                    for (int h = 0; h < 2; h++) {
                        int s = mf*2 + h;
                        float v0 = fmaf(-2.0f, acc[mf][nf][2*h],     e0);
                        float v1 = fmaf(-2.0f, acc[mf][nf][2*h + 1], e1);
                        if (v0 < bv0[s]) { bv1[s]=bv0[s]; bi1[s]=bi0[s]; bv0[s]=v0; bi0[s]=col; }
                        else if (v0 < bv1[s]) { bv1[s]=v0; bi1[s]=col; }
                        if (v1 < bv0[s]) { bv1[s]=bv0[s]; bi1[s]=bi0[s]; bv0[s]=v1; bi0[s]=col+1; }
                        else if (v1 < bv1[s]) { bv1[s]=v1; bi1[s]=col+1; }
                    }
            }
        }
    }

    __syncthreads();
    float* redV = (float*)smem;                 // [128][16][2]
    int*   redI = (int*)(smem + 16384);
    int slot16 = wn*4 + (lane & 3);
    #pragma unroll
    for (int mf = 0; mf < 2; mf++)
        #pragma unroll
        for (int h = 0; h < 2; h++) {
            int s = mf*2 + h;
            int r = wm*32 + mf*16 + (lane >> 2) + h*8;
            redV[(r*16 + slot16)*2 + 0] = bv0[s];
            redV[(r*16 + slot16)*2 + 1] = bv1[s];
            redI[(r*16 + slot16)*2 + 0] = bi0[s];
            redI[(r*16 + slot16)*2 + 1] = bi1[s];
        }
    __syncthreads();
    if (tid < 128) {
        float tv0=3.4e38f, tv1=3.4e38f, tv2=3.4e38f, tv3=3.4e38f;
        int   ti0=0, ti1=0, ti2=0, ti3=0;
        #pragma unroll
        for (int s = 0; s < 32; s++) {
            float v = redV[tid*32 + s]; int iv = redI[tid*32 + s];
            if (v < tv3 || (v == tv3 && iv < ti3)) {
                tv3 = v; ti3 = iv;
                if (tv3 < tv2 || (tv3 == tv2 && ti3 < ti2)) {
                    float tv = tv2; int ti = ti2; tv2 = tv3; ti2 = ti3; tv3 = tv; ti3 = ti; }
                if (tv2 < tv1 || (tv2 == tv1 && ti2 < ti1)) {
                    float tv = tv1; int ti = ti1; tv1 = tv2; ti1 = ti2; tv2 = tv; ti2 = ti; }
                if (tv1 < tv0 || (tv1 == tv0 && ti1 < ti0)) {
                    float tv = tv0; int ti = ti0; tv0 = tv1; ti0 = ti1; tv1 = tv; ti1 = ti; }
            }
        }
        g_cand[tokbase + tid] = make_int4(ti0, ti1, ti2, ti3);
    }
}

// =====================================================================
// Fused exact rescore (4 candidates) + quantized output + scatter + diff.
// One block (256 threads) per token.
// =====================================================================
__global__ void k_finalize(const float* __restrict__ x, float* __restrict__ out,
                           float* __restrict__ out_ids_f) {
    __shared__ float sred[4][8];
    __shared__ int   sbest;
    int t = blockIdx.x;
    int l = (t / SDIM) % LDIM;
    int d = threadIdx.x, lane = d & 31, w = d >> 5;
    int4 c = g_cand[t];

    float xv = x[(size_t)t*DDIM + d];
    const float* eb = g_embedT + (size_t)l*EDIM*DDIM;
    float p0 = xv * eb[(size_t)c.x*DDIM + d];
    float p1 = xv * eb[(size_t)c.y*DDIM + d];
    float p2 = xv * eb[(size_t)c.z*DDIM + d];
    float p3 = xv * eb[(size_t)c.w*DDIM + d];
    #pragma unroll
    for (int o = 16; o > 0; o >>= 1) {
        p0 += __shfl_down_sync(0xffffffffu, p0, o);
        p1 += __shfl_down_sync(0xffffffffu, p1, o);
        p2 += __shfl_down_sync(0xffffffffu, p2, o);
        p3 += __shfl_down_sync(0xffffffffu, p3, o);
    }
    if (lane == 0) { sred[0][w]=p0; sred[1][w]=p1; sred[2][w]=p2; sred[3][w]=p3; }
    __syncthreads();
    if (d == 0) {
        const float* en = g_enorm + l*EDIM;
        float dts[4];
        #pragma unroll
        for (int i = 0; i < 4; i++) {
            float s = 0.f;
            #pragma unroll
            for (int ww = 0; ww < 8; ww++) s += sred[i][ww];
            dts[i] = s;
        }
        int   ci[4] = {c.x, c.y, c.z, c.w};
        float bs = fmaf(-2.0f, dts[0], en[ci[0]]); int bi = ci[0];
        #pragma unroll
        for (int i = 1; i < 4; i++) {
            float sc = fmaf(-2.0f, dts[i], en[ci[i]]);
            if (sc < bs || (sc == bs && ci[i] < bi)) { bs = sc; bi = ci[i]; }
        }
        sbest = bi;
        out_ids_f[t] = (float)bi;
    }
    __syncthreads();
    int e = sbest;

    size_t ced = ((size_t)l*EDIM + e)*DDIM + d;
    float qv = g_embedT[ced];
    out[(size_t)t*DDIM + d] = qv;

    long long fx = llrint((double)xv * 4294967296.0);
    atomicAdd((unsigned long long*)&g_sum[ced], (unsigned long long)fx);
    if (d == 0) atomicAdd(&g_counts[l*EDIM + e], 1);

    if (l == LDIM - 1) {
        __shared__ long long dred[8];
        float df = (qv - xv)*(qv - xv);
        long long fd = llrint((double)df * 1048576.0);
        #pragma unroll
        for (int o = 16; o > 0; o >>= 1) fd += __shfl_down_sync(0xffffffffu, fd, o);
        if (lane == 0) dred[w] = fd;
        __syncthreads();
        if (d == 0) {
            long long s = 0;
            #pragma unroll
            for (int ww = 0; ww < 8; ww++) s += dred[ww];
            atomicAdd(&g_diffacc, (unsigned long long)s);
        }
    }
}

// =====================================================================
__global__ void k_ncs(const float* __restrict__ cs_in,
                      float* __restrict__ out_ncs, float* __restrict__ out_diff) {
    int l = blockIdx.x;
    __shared__ float red[32];
    float local = 0.f;
    for (int e = threadIdx.x; e < EDIM; e += blockDim.x) {
        float v = 0.999f*cs_in[l*EDIM+e] + 0.001f*(float)g_counts[l*EDIM+e];
        out_ncs[l*EDIM+e] = v;
        local += v;
    }
    #pragma unroll
    for (int o = 16; o > 0; o >>= 1) local += __shfl_down_sync(0xffffffffu, local, o);
    if ((threadIdx.x & 31) == 0) red[threadIdx.x >> 5] = local;
    __syncthreads();
    if (threadIdx.x < 32) {
        float v = red[threadIdx.x];
        #pragma unroll
        for (int o = 16; o > 0; o >>= 1) v += __shfl_down_sync(0xffffffffu, v, o);
        if (threadIdx.x == 0) g_nvals[l] = v;
    }
    if (l == 0 && threadIdx.x == 0) {
        double dsum = (double)(long long)g_diffacc * (1.0/1048576.0);
        out_diff[0] = (float)(2.0 * (dsum / (double)((size_t)BDIM*SDIM*DDIM)) / (double)LDIM);
    }
}

__global__ void k_final(const float* __restrict__ embed_avg,
                        const float* __restrict__ out_ncs,
                        float* __restrict__ out_ne, float* __restrict__ out_nea) {
    __shared__ long long tile[32][33];
    int l  = blockIdx.z;
    int e0 = blockIdx.x * 32;
    int d0 = blockIdx.y * 32;
    int tx = threadIdx.x, ty = threadIdx.y;   // 32 x 8
    #pragma unroll
    for (int i = ty; i < 32; i += 8)
        tile[i][tx] = g_sum[((size_t)(l*EDIM + e0 + i))*DDIM + d0 + tx];
    __syncthreads();
    float n   = g_nvals[l];
    float ncs = out_ncs[l*EDIM + e0 + tx];
    float cs  = (ncs + 1e-5f) / (n + 0.02048f) * n;
    #pragma unroll
    for (int i = ty; i < 32; i += 8) {
        size_t o = ((size_t)l*DDIM + d0 + i)*EDIM + e0 + tx;
        float sum = (float)((double)tile[tx][i] * (1.0/4294967296.0));
        float nea = 0.999f*embed_avg[o] + 0.001f*sum;
        out_nea[o] = nea;
        out_ne[o]  = nea / cs;
    }
}

// =====================================================================
extern "C" void kernel_launch(void* const* d_in, const int* in_sizes, int n_in,
                              void* d_out, int out_size) {
    const float* x     = (const float*)d_in[0];
    const float* embed = (const float*)d_in[1];
    const float* csz   = (const float*)d_in[2];
    const float* eavg  = (const float*)d_in[3];

    float* out      = (float*)d_out;
    float* out_main = out;
    float* out_diff = out + (size_t)33554432;
    float* out_ids  = out + (size_t)33554433;
    float* out_ne   = out_ids + (size_t)131072;
    float* out_ncs  = out_ne  + (size_t)4194304;
    float* out_nea  = out_ncs + (size_t)16384;

    cudaFuncSetAttribute(k_assign_mma, cudaFuncAttributeMaxDynamicSharedMemorySize,
                         SMEM_TOTAL);

    void *pSum, *pCnt, *pDiff;
    cudaGetSymbolAddress(&pSum,  g_sum);
    cudaGetSymbolAddress(&pCnt,  g_counts);
    cudaGetSymbolAddress(&pDiff, g_diffacc);
    cudaMemsetAsync(pSum,  0, (size_t)LDIM*EDIM*DDIM*sizeof(long long));
    cudaMemsetAsync(pCnt,  0, (size_t)LDIM*EDIM*sizeof(int));
    cudaMemsetAsync(pDiff, 0, sizeof(unsigned long long));

    dim3 tb(32, 8);
    k_enorm<<<(LDIM*EDIM)/256, 256>>>(embed);
    k_expand_x<<<NTOK, 128>>>(x);
    k_expand_e<<<dim3(EDIM/32, DDIM/32, LDIM), tb>>>(embed);
    k_assign_mma<<<dim3(TOKL/128, LDIM), 512, SMEM_TOTAL>>>(0);
    k_finalize<<<NTOK, 256>>>(x, out_main, out_ids);
    k_ncs<<<LDIM, 1024>>>(csz, out_ncs, out_diff);
    k_final<<<dim3(EDIM/32, DDIM/32, LDIM), tb>>>(eavg, out_ncs, out_ne, out_nea);
}